// round 2
// baseline (speedup 1.0000x reference)
#include <cuda_runtime.h>
#include <math.h>

// Problem dims
#define NB 2048
#define NT 512
#define NP 8
#define NL 64
#define NH 180
#define NH3 540

#define RT 16          // batch rows per CTA
#define NCTA (NB/RT)   // 128
#define THREADS 256

// -------- transposed (K-major) weights in device globals (scratch, no alloc) -----
__device__ float g_WTin[(NP+NL)*NH];   // [72][180]
__device__ float g_WThp[NL*NH];        // [64][180]
__device__ float g_WTih[NH*NH3];       // [180][540]
__device__ float g_WThh[NH*NH3];       // [180][540]
__device__ float g_WTo1[(NH+NL)*NH];   // [244][180]
__device__ float g_WTo2[NH*NL];        // [180][64]

__global__ void transpose_k(const float* __restrict__ src, float* __restrict__ dst,
                            int O, int K) {
    int i = blockIdx.x * blockDim.x + threadIdx.x;
    if (i < O * K) {
        int o = i / K;
        int k = i - o * K;
        dst[k * O + o] = src[i];
    }
}

__device__ __forceinline__ float gelu_f(float x) {
    return 0.5f * x * (1.0f + erff(x * 0.7071067811865476f));
}

__device__ __forceinline__ float sigmoid_f(float x) {
    return 1.0f / (1.0f + expf(-x));
}

// Y[16][O] = act(A[16][K] @ WT[K][O] + bias)
// 256 threads: rg = tid>>7 picks rows [rg*8, rg*8+8), cl = tid&127 picks cols cl+128j.
template<int K, int O, int TNc, bool ACT>
__device__ __forceinline__ void gemm16(const float* __restrict__ sA,
                                       const float* __restrict__ WT,
                                       const float* __restrict__ bias,
                                       float* __restrict__ sY,
                                       int rg, int cl)
{
    float acc[8][TNc];
#pragma unroll
    for (int r = 0; r < 8; r++)
#pragma unroll
        for (int j = 0; j < TNc; j++) acc[r][j] = 0.0f;

    const float* A0 = sA + rg * (8 * K);

#pragma unroll 2
    for (int k = 0; k < K; k += 4) {
        float w[4][TNc];
#pragma unroll
        for (int j = 0; j < TNc; j++) {
            int c = cl + 128 * j;
            bool v = (c < O);
#pragma unroll
            for (int kk = 0; kk < 4; kk++)
                w[kk][j] = v ? WT[(k + kk) * O + c] : 0.0f;
        }
#pragma unroll
        for (int r = 0; r < 8; r++) {
            float4 a = *reinterpret_cast<const float4*>(A0 + r * K + k);
#pragma unroll
            for (int j = 0; j < TNc; j++) {
                float s = acc[r][j];
                s = fmaf(a.x, w[0][j], s);
                s = fmaf(a.y, w[1][j], s);
                s = fmaf(a.z, w[2][j], s);
                s = fmaf(a.w, w[3][j], s);
                acc[r][j] = s;
            }
        }
    }

#pragma unroll
    for (int j = 0; j < TNc; j++) {
        int c = cl + 128 * j;
        if (c < O) {
            float bb = bias[c];
#pragma unroll
            for (int r = 0; r < 8; r++) {
                float v = acc[r][j] + bb;
                if (ACT) v = gelu_f(v);
                sY[(rg * 8 + r) * O + c] = v;
            }
        }
    }
}

// SMEM layout sizes (floats)
#define SZ_IN  (RT*(NP+NL))   // 16*72
#define SZ_X   (RT*NH)        // 16*180
#define SZ_H   (RT*NH)
#define SZ_GI  (RT*NH3)       // 16*540
#define SZ_GH  (RT*NH3)
#define SZ_HC  (RT*(NH+NL))   // 16*244
#define SZ_O   (RT*NH)
#define SZ_CUR (RT*NL)        // 16*64
#define SMEM_FLOATS (SZ_IN+SZ_X+SZ_H+SZ_GI+SZ_GH+SZ_HC+SZ_O+SZ_CUR)
#define SMEM_BYTES (SMEM_FLOATS*4)

__global__ __launch_bounds__(THREADS, 1)
void rnn_kernel(const float* __restrict__ phys,
                const float* __restrict__ latents,
                const float* __restrict__ b_in,
                const float* __restrict__ b_hp,
                const float* __restrict__ b_ih,
                const float* __restrict__ b_hh,
                const float* __restrict__ b_o1,
                const float* __restrict__ b_o2,
                float* __restrict__ out)
{
    extern __shared__ float sm[];
    float* sIn  = sm;
    float* sX   = sIn  + SZ_IN;
    float* sH   = sX   + SZ_X;
    float* sGi  = sH   + SZ_H;
    float* sGh  = sGi  + SZ_GI;
    float* sHC  = sGh  + SZ_GH;
    float* sO   = sHC  + SZ_HC;
    float* sCur = sO   + SZ_O;

    const int tid = threadIdx.x;
    const int rg  = tid >> 7;    // row group 0/1 -> rows rg*8..rg*8+7
    const int cl  = tid & 127;   // column lane
    const int b0  = blockIdx.x * RT;

    // init: cur = latents; h0 = latents @ W_hp^T + b_hp
    for (int i = tid; i < RT * NL; i += THREADS) {
        int r = i >> 6, l = i & 63;
        sCur[i] = latents[(size_t)(b0 + r) * NL + l];
    }
    __syncthreads();
    gemm16<NL, NH, 2, false>(sCur, g_WThp, b_hp, sH, rg, cl);
    __syncthreads();

    for (int t = 0; t < NT; t++) {
        // build sIn = [phys_t | cur]  -> [16][72]
        for (int i = tid; i < RT * NP; i += THREADS) {
            int r = i >> 3, p = i & 7;
            sIn[r * (NP + NL) + p] =
                phys[((size_t)(b0 + r) * NT + t) * NP + p];
        }
        for (int i = tid; i < RT * NL; i += THREADS) {
            int r = i >> 6, l = i & 63;
            sIn[r * (NP + NL) + NP + l] = sCur[i];
        }
        __syncthreads();

        // x = gelu(in @ W_in^T + b_in)   [16][180]
        gemm16<(NP + NL), NH, 2, true>(sIn, g_WTin, b_in, sX, rg, cl);
        __syncthreads();

        // gi = x @ W_ih^T + b_ih ; gh = h @ W_hh^T + b_hh   [16][540]
        gemm16<NH, NH3, 5, false>(sX, g_WTih, b_ih, sGi, rg, cl);
        gemm16<NH, NH3, 5, false>(sH, g_WThh, b_hh, sGh, rg, cl);
        __syncthreads();

        // GRU gates -> h_new ; also pack hcat = [h_new | cur]
        for (int i = tid; i < RT * NH; i += THREADS) {
            int r = i / NH;
            int j = i - r * NH;
            float gir = sGi[r * NH3 + j];
            float giz = sGi[r * NH3 + NH + j];
            float gin = sGi[r * NH3 + 2 * NH + j];
            float ghr = sGh[r * NH3 + j];
            float ghz = sGh[r * NH3 + NH + j];
            float ghn = sGh[r * NH3 + 2 * NH + j];
            float rr = sigmoid_f(gir + ghr);
            float zz = sigmoid_f(giz + ghz);
            float nn = tanhf(gin + rr * ghn);
            float hn = (1.0f - zz) * nn + zz * sH[r * NH + j];
            sH[r * NH + j] = hn;
            sHC[r * (NH + NL) + j] = hn;
        }
        for (int i = tid; i < RT * NL; i += THREADS) {
            int r = i >> 6, l = i & 63;
            sHC[r * (NH + NL) + NH + l] = sCur[i];
        }
        __syncthreads();

        // o = gelu(hcat @ W_o1^T + b_o1)  [16][180]
        gemm16<(NH + NL), NH, 2, true>(sHC, g_WTo1, b_o1, sO, rg, cl);
        __syncthreads();

        // delta = o @ W_o2^T + b_o2 ; cur = clip(cur + delta, 0, 1) ; write out
        if (cl < NL) {
            float acc[8];
#pragma unroll
            for (int r = 0; r < 8; r++) acc[r] = 0.0f;
            const float* A0 = sO + rg * (8 * NH);
#pragma unroll 2
            for (int k = 0; k < NH; k += 4) {
                float w0 = g_WTo2[(k + 0) * NL + cl];
                float w1 = g_WTo2[(k + 1) * NL + cl];
                float w2 = g_WTo2[(k + 2) * NL + cl];
                float w3 = g_WTo2[(k + 3) * NL + cl];
#pragma unroll
                for (int r = 0; r < 8; r++) {
                    float4 a = *reinterpret_cast<const float4*>(A0 + r * NH + k);
                    float s = acc[r];
                    s = fmaf(a.x, w0, s);
                    s = fmaf(a.y, w1, s);
                    s = fmaf(a.z, w2, s);
                    s = fmaf(a.w, w3, s);
                    acc[r] = s;
                }
            }
            float bb = b_o2[cl];
#pragma unroll
            for (int r = 0; r < 8; r++) {
                int rr = rg * 8 + r;
                float c = sCur[rr * NL + cl] + acc[r] + bb;
                c = fminf(fmaxf(c, 0.0f), 1.0f);
                sCur[rr * NL + cl] = c;
                out[((size_t)(b0 + rr) * NT + t) * NL + cl] = c;
            }
        }
        __syncthreads();
    }
}

extern "C" void kernel_launch(void* const* d_in, const int* in_sizes, int n_in,
                              void* d_out, int out_size)
{
    const float* phys    = (const float*)d_in[0];
    const float* latents = (const float*)d_in[1];
    const float* W_in    = (const float*)d_in[2];
    const float* b_in    = (const float*)d_in[3];
    const float* W_hp    = (const float*)d_in[4];
    const float* b_hp    = (const float*)d_in[5];
    const float* W_ih    = (const float*)d_in[6];
    const float* b_ih    = (const float*)d_in[7];
    const float* W_hh    = (const float*)d_in[8];
    const float* b_hh    = (const float*)d_in[9];
    const float* W_o1    = (const float*)d_in[10];
    const float* b_o1    = (const float*)d_in[11];
    const float* W_o2    = (const float*)d_in[12];
    const float* b_o2    = (const float*)d_in[13];
    float* out = (float*)d_out;

    float *pWTin, *pWThp, *pWTih, *pWThh, *pWTo1, *pWTo2;
    cudaGetSymbolAddress((void**)&pWTin, g_WTin);
    cudaGetSymbolAddress((void**)&pWThp, g_WThp);
    cudaGetSymbolAddress((void**)&pWTih, g_WTih);
    cudaGetSymbolAddress((void**)&pWThh, g_WThh);
    cudaGetSymbolAddress((void**)&pWTo1, g_WTo1);
    cudaGetSymbolAddress((void**)&pWTo2, g_WTo2);

    const int bs = 256;
    transpose_k<<<(NH * (NP + NL) + bs - 1) / bs, bs>>>(W_in, pWTin, NH, NP + NL);
    transpose_k<<<(NH * NL + bs - 1) / bs, bs>>>(W_hp, pWThp, NH, NL);
    transpose_k<<<(NH3 * NH + bs - 1) / bs, bs>>>(W_ih, pWTih, NH3, NH);
    transpose_k<<<(NH3 * NH + bs - 1) / bs, bs>>>(W_hh, pWThh, NH3, NH);
    transpose_k<<<(NH * (NH + NL) + bs - 1) / bs, bs>>>(W_o1, pWTo1, NH, NH + NL);
    transpose_k<<<(NL * NH + bs - 1) / bs, bs>>>(W_o2, pWTo2, NL, NH);

    cudaFuncSetAttribute(rnn_kernel,
                         cudaFuncAttributeMaxDynamicSharedMemorySize, SMEM_BYTES);
    rnn_kernel<<<NCTA, THREADS, SMEM_BYTES>>>(phys, latents, b_in, b_hp,
                                              b_ih, b_hh, b_o1, b_o2, out);
}

// round 3
// speedup vs baseline: 1.2982x; 1.2982x over previous
#include <cuda_runtime.h>
#include <math.h>

// Problem dims
#define NB 2048
#define NT 512
#define NP 8
#define NL 64
#define NH 180
#define NH3 540
#define KIN (NP+NL)     // 72
#define KO1 (NH+NL)     // 244

#define RT 16           // batch rows per CTA
#define NCTA (NB/RT)    // 128
#define THREADS 256

// -------- K-major (transposed) weights in device globals --------
__device__ float g_WTin[KIN*NH];
__device__ float g_WThp[NL*NH];
__device__ float g_WTih[NH*NH3];
__device__ float g_WThh[NH*NH3];
__device__ float g_WTo1[KO1*NH];
__device__ float g_WTo2[NH*NL];

struct TJobs {
    const float* src0; float* dst0; int O0, K0;
    const float* src1; float* dst1; int O1, K1;
    const float* src2; float* dst2; int O2, K2;
    const float* src3; float* dst3; int O3, K3;
};

__global__ void transpose_multi(TJobs j) {
    int i = blockIdx.x * blockDim.x + threadIdx.x;
    int n0 = j.O0 * j.K0;
    if (i < n0) { int o = i / j.K0, k = i - o * j.K0; j.dst0[k * j.O0 + o] = j.src0[i]; return; }
    i -= n0;
    int n1 = j.O1 * j.K1;
    if (i < n1) { int o = i / j.K1, k = i - o * j.K1; j.dst1[k * j.O1 + o] = j.src1[i]; return; }
    i -= n1;
    int n2 = j.O2 * j.K2;
    if (i < n2) { int o = i / j.K2, k = i - o * j.K2; j.dst2[k * j.O2 + o] = j.src2[i]; return; }
    i -= n2;
    int n3 = j.O3 * j.K3;
    if (i < n3) { int o = i / j.K3, k = i - o * j.K3; j.dst3[k * j.O3 + o] = j.src3[i]; return; }
}

__device__ __forceinline__ float gelu_f(float x) {
    return 0.5f * x * (1.0f + erff(x * 0.7071067811865476f));
}
__device__ __forceinline__ float sigmoid_f(float x) {
    return 1.0f / (1.0f + expf(-x));
}

// FMA block: 16 rows x NC cols x 4 k's
template<int K, int NC>
__device__ __forceinline__ void fma16(const float* __restrict__ sA, int k,
                                      const float (&w)[4][NC], float (&acc)[16][NC]) {
#pragma unroll
    for (int r = 0; r < 16; r++) {
        float4 a = *reinterpret_cast<const float4*>(sA + r * K + k);
#pragma unroll
        for (int j = 0; j < NC; j++) {
            float s = acc[r][j];
            s = fmaf(a.x, w[0][j], s);
            s = fmaf(a.y, w[1][j], s);
            s = fmaf(a.z, w[2][j], s);
            s = fmaf(a.w, w[3][j], s);
            acc[r][j] = s;
        }
    }
}

// Y[16][O] = act(A[16][K] @ WT[K][O] + bias) for this thread's NC columns.
// Weight loads register-double-buffered to hide L2 latency.
template<int K, int O, int NC, bool ACT>
__device__ __forceinline__ void gemmN(const float* __restrict__ sA,
                                      const float* __restrict__ W,
                                      const float* __restrict__ bias,
                                      float* __restrict__ sY,
                                      const int (&c)[NC], const bool (&st)[NC])
{
    float acc[16][NC];
#pragma unroll
    for (int r = 0; r < 16; r++)
#pragma unroll
        for (int j = 0; j < NC; j++) acc[r][j] = 0.0f;

    float w[4][NC];
#pragma unroll
    for (int j = 0; j < NC; j++)
#pragma unroll
        for (int kk = 0; kk < 4; kk++) w[kk][j] = W[kk * O + c[j]];

#pragma unroll 1
    for (int k = 0; k + 4 < K; k += 4) {
        float wn[4][NC];
#pragma unroll
        for (int j = 0; j < NC; j++)
#pragma unroll
            for (int kk = 0; kk < 4; kk++) wn[kk][j] = W[(k + 4 + kk) * O + c[j]];
        fma16<K, NC>(sA, k, w, acc);
#pragma unroll
        for (int j = 0; j < NC; j++)
#pragma unroll
            for (int kk = 0; kk < 4; kk++) w[kk][j] = wn[kk][j];
    }
    fma16<K, NC>(sA, K - 4, w, acc);

#pragma unroll
    for (int j = 0; j < NC; j++) {
        if (st[j]) {
            float bb = bias[c[j]];
#pragma unroll
            for (int r = 0; r < 16; r++) {
                float v = acc[r][j] + bb;
                if (ACT) v = gelu_f(v);
                sY[r * O + c[j]] = v;
            }
        }
    }
}

// Dispatch a 540-col GEMM: every thread owns cols {tid, tid+256};
// warp 'xw' additionally owns col 512+lane (lanes 0..27).
template<int K, bool ACT>
__device__ __forceinline__ void gemm540(const float* __restrict__ sA,
                                        const float* __restrict__ W,
                                        const float* __restrict__ bias,
                                        float* __restrict__ sY,
                                        int tid, int xw)
{
    int wid = tid >> 5, lane = tid & 31;
    if (wid == xw) {
        int c[3] = { tid, tid + 256, 512 + (lane < 28 ? lane : 27) };
        bool st[3] = { true, true, lane < 28 };
        gemmN<K, NH3, 3, ACT>(sA, W, bias, sY, c, st);
    } else {
        int c[2] = { tid, tid + 256 };
        bool st[2] = { true, true };
        gemmN<K, NH3, 2, ACT>(sA, W, bias, sY, c, st);
    }
}

// SMEM layout sizes (floats)
#define SZ_IN  (RT*KIN)
#define SZ_X   (RT*NH)
#define SZ_H   (RT*NH)
#define SZ_GI  (RT*NH3)
#define SZ_GH  (RT*NH3)
#define SZ_HC  (RT*KO1)
#define SZ_O   (RT*NH)
#define SZ_CUR (RT*NL)
#define SMEM_FLOATS (SZ_IN+SZ_X+SZ_H+SZ_GI+SZ_GH+SZ_HC+SZ_O+SZ_CUR)
#define SMEM_BYTES (SMEM_FLOATS*4)

__global__ __launch_bounds__(THREADS, 1)
void rnn_kernel(const float* __restrict__ phys,
                const float* __restrict__ latents,
                const float* __restrict__ b_in,
                const float* __restrict__ b_hp,
                const float* __restrict__ b_ih,
                const float* __restrict__ b_hh,
                const float* __restrict__ b_o1,
                const float* __restrict__ b_o2,
                float* __restrict__ out)
{
    extern __shared__ float sm[];
    float* sIn  = sm;
    float* sX   = sIn  + SZ_IN;
    float* sH   = sX   + SZ_X;
    float* sGi  = sH   + SZ_H;
    float* sGh  = sGi  + SZ_GI;
    float* sHC  = sGh  + SZ_GH;
    float* sO   = sHC  + SZ_HC;
    float* sCur = sO   + SZ_O;

    const int tid = threadIdx.x;
    const int b0  = blockIdx.x * RT;

    // init: cur = latents
    for (int i = tid; i < RT * NL; i += THREADS) {
        int r = i >> 6, l = i & 63;
        sCur[i] = latents[(size_t)(b0 + r) * NL + l];
    }
    __syncthreads();
    // h0 = latents @ W_hp^T + b_hp (threads 0..179, one col each)
    if (tid < NH) {
        int c[1] = { tid };
        bool st[1] = { true };
        gemmN<NL, NH, 1, false>(sCur, g_WThp, b_hp, sH, c, st);
    }
    // (visibility of sH guaranteed by the sync after sIn build below)

#pragma unroll 1
    for (int t = 0; t < NT; t++) {
        // build sIn = [phys_t | cur]
        for (int i = tid; i < RT * NP; i += THREADS) {
            int r = i >> 3, p = i & 7;
            sIn[r * KIN + p] = phys[((size_t)(b0 + r) * NT + t) * NP + p];
        }
        for (int i = tid; i < RT * NL; i += THREADS) {
            int r = i >> 6, l = i & 63;
            sIn[r * KIN + NP + l] = sCur[i];
        }
        __syncthreads();   // sIn ready (also orders prev-step sH writes / h0)

        // gh = h @ W_hh^T + b_hh (all threads; extra cols on warp 7)
        gemm540<NH, false>(sH, g_WThh, b_hh, sGh, tid, 7);
        // x = gelu(in @ W_in^T + b_in) (threads 0..179)
        if (tid < NH) {
            int c[1] = { tid };
            bool st[1] = { true };
            gemmN<KIN, NH, 1, true>(sIn, g_WTin, b_in, sX, c, st);
        }
        __syncthreads();   // sX (and sGh) ready

        // gi = x @ W_ih^T + b_ih (all threads; extra cols on warp 6)
        gemm540<NH, false>(sX, g_WTih, b_ih, sGi, tid, 6);
        __syncthreads();   // sGi ready

        // GRU gates -> h_new; pack hcat = [h_new | cur]
        for (int i = tid; i < RT * NH; i += THREADS) {
            int r = i / NH;
            int j = i - r * NH;
            float gir = sGi[r * NH3 + j];
            float giz = sGi[r * NH3 + NH + j];
            float gin = sGi[r * NH3 + 2 * NH + j];
            float ghr = sGh[r * NH3 + j];
            float ghz = sGh[r * NH3 + NH + j];
            float ghn = sGh[r * NH3 + 2 * NH + j];
            float rr = sigmoid_f(gir + ghr);
            float zz = sigmoid_f(giz + ghz);
            float nn = tanhf(gin + rr * ghn);
            float hn = (1.0f - zz) * nn + zz * sH[r * NH + j];
            sH[r * NH + j] = hn;
            sHC[r * KO1 + j] = hn;
        }
        for (int i = tid; i < RT * NL; i += THREADS) {
            int r = i >> 6, l = i & 63;
            sHC[r * KO1 + NH + l] = sCur[i];
        }
        __syncthreads();   // sHC, sH ready

        // o = gelu(hcat @ W_o1^T + b_o1) (threads 0..179)
        if (tid < NH) {
            int c[1] = { tid };
            bool st[1] = { true };
            gemmN<KO1, NH, 1, true>(sHC, g_WTo1, b_o1, sO, c, st);
        }
        __syncthreads();   // sO ready

        // delta = o @ W_o2^T + b_o2; cur = clip(cur + delta); write out
        {
            int col = tid & 63;
            int rg2 = tid >> 6;                // 4 rows per thread
            const float* A0 = sO + rg2 * 4 * NH;
            float acc[4] = {0.f, 0.f, 0.f, 0.f};
            float w[4];
#pragma unroll
            for (int kk = 0; kk < 4; kk++) w[kk] = g_WTo2[kk * NL + col];
#pragma unroll 1
            for (int k = 0; k + 4 < NH; k += 4) {
                float wn[4];
#pragma unroll
                for (int kk = 0; kk < 4; kk++) wn[kk] = g_WTo2[(k + 4 + kk) * NL + col];
#pragma unroll
                for (int r = 0; r < 4; r++) {
                    float4 a = *reinterpret_cast<const float4*>(A0 + r * NH + k);
                    float s = acc[r];
                    s = fmaf(a.x, w[0], s);
                    s = fmaf(a.y, w[1], s);
                    s = fmaf(a.z, w[2], s);
                    s = fmaf(a.w, w[3], s);
                    acc[r] = s;
                }
#pragma unroll
                for (int kk = 0; kk < 4; kk++) w[kk] = wn[kk];
            }
#pragma unroll
            for (int r = 0; r < 4; r++) {
                float4 a = *reinterpret_cast<const float4*>(A0 + r * NH + (NH - 4));
                float s = acc[r];
                s = fmaf(a.x, w[0], s);
                s = fmaf(a.y, w[1], s);
                s = fmaf(a.z, w[2], s);
                s = fmaf(a.w, w[3], s);
                acc[r] = s;
            }
            float bb = b_o2[col];
#pragma unroll
            for (int r = 0; r < 4; r++) {
                int row = rg2 * 4 + r;
                float c = sCur[row * NL + col] + acc[r] + bb;
                c = fminf(fmaxf(c, 0.0f), 1.0f);
                sCur[row * NL + col] = c;
                out[((size_t)(b0 + row) * NT + t) * NL + col] = c;
            }
        }
        __syncthreads();   // sCur ready for next step
    }
}

extern "C" void kernel_launch(void* const* d_in, const int* in_sizes, int n_in,
                              void* d_out, int out_size)
{
    const float* phys    = (const float*)d_in[0];
    const float* latents = (const float*)d_in[1];
    const float* W_in    = (const float*)d_in[2];
    const float* b_in    = (const float*)d_in[3];
    const float* W_hp    = (const float*)d_in[4];
    const float* b_hp    = (const float*)d_in[5];
    const float* W_ih    = (const float*)d_in[6];
    const float* b_ih    = (const float*)d_in[7];
    const float* W_hh    = (const float*)d_in[8];
    const float* b_hh    = (const float*)d_in[9];
    const float* W_o1    = (const float*)d_in[10];
    const float* b_o1    = (const float*)d_in[11];
    const float* W_o2    = (const float*)d_in[12];
    const float* b_o2    = (const float*)d_in[13];
    float* out = (float*)d_out;

    float *pWTin, *pWThp, *pWTih, *pWThh, *pWTo1, *pWTo2;
    cudaGetSymbolAddress((void**)&pWTin, g_WTin);
    cudaGetSymbolAddress((void**)&pWThp, g_WThp);
    cudaGetSymbolAddress((void**)&pWTih, g_WTih);
    cudaGetSymbolAddress((void**)&pWThh, g_WThh);
    cudaGetSymbolAddress((void**)&pWTo1, g_WTo1);
    cudaGetSymbolAddress((void**)&pWTo2, g_WTo2);

    // exactly 3 launches per call so ncu -s 5 -c 1 captures rnn_kernel
    TJobs jb1 = { W_ih, pWTih, NH3, NH,
                  W_hh, pWThh, NH3, NH,
                  nullptr, nullptr, 0, 0,
                  nullptr, nullptr, 0, 0 };
    TJobs jb2 = { W_in, pWTin, NH, KIN,
                  W_hp, pWThp, NH, NL,
                  W_o1, pWTo1, NH, KO1,
                  W_o2, pWTo2, NL, NH };
    const int bs = 256;
    transpose_multi<<<(2 * NH3 * NH + bs - 1) / bs, bs>>>(jb1);
    transpose_multi<<<(NH * (KIN + NL + KO1) + NL * NH + bs - 1) / bs, bs>>>(jb2);

    cudaFuncSetAttribute(rnn_kernel,
                         cudaFuncAttributeMaxDynamicSharedMemorySize, SMEM_BYTES);
    rnn_kernel<<<NCTA, THREADS, SMEM_BYTES>>>(phys, latents, b_in, b_hp,
                                              b_ih, b_hh, b_o1, b_o2, out);
}